// round 1
// baseline (speedup 1.0000x reference)
#include <cuda_runtime.h>
#include <math.h>

// Problem constants (B=4, T=2048, D=1024, E=8, K=2)
#define BT   8192
#define DD   1024
#define EE   8
#define TPB  256

__device__ double g_aux_sum;

__global__ void rlgate_init_kernel() {
    g_aux_sum = 0.0;
}

__global__ __launch_bounds__(TPB) void rlgate_main_kernel(
    const float* __restrict__ x,          // [BT, D]
    const float* __restrict__ eo,         // [E, BT, D]
    const float* __restrict__ rewards,    // [BT]
    const float* __restrict__ W,          // [D, E]
    const float* __restrict__ bias,       // [E]
    const float* __restrict__ baseline,   // scalar
    const float* __restrict__ noise,      // [BT, E]
    float* __restrict__ out)              // [BT, D] (+ aux at end, written elsewhere)
{
    const int row  = blockIdx.x;
    const int tid  = threadIdx.x;
    const int lane = tid & 31;
    const int warp = tid >> 5;

    __shared__ float s_part[EE][TPB / 32];
    __shared__ float s_logit[EE];
    __shared__ int   s_idx[2];

    // ---- Phase 1: logits = x[row,:] @ W + b ----
    const float* xr = x + (size_t)row * DD;
    float acc[EE];
#pragma unroll
    for (int e = 0; e < EE; e++) acc[e] = 0.0f;

    for (int d = tid; d < DD; d += TPB) {
        float xv = __ldg(xr + d);
        const float4* wr = (const float4*)(W + (size_t)d * EE);
        float4 w0 = __ldg(wr);
        float4 w1 = __ldg(wr + 1);
        acc[0] = fmaf(xv, w0.x, acc[0]);
        acc[1] = fmaf(xv, w0.y, acc[1]);
        acc[2] = fmaf(xv, w0.z, acc[2]);
        acc[3] = fmaf(xv, w0.w, acc[3]);
        acc[4] = fmaf(xv, w1.x, acc[4]);
        acc[5] = fmaf(xv, w1.y, acc[5]);
        acc[6] = fmaf(xv, w1.z, acc[6]);
        acc[7] = fmaf(xv, w1.w, acc[7]);
    }

#pragma unroll
    for (int e = 0; e < EE; e++) {
#pragma unroll
        for (int off = 16; off > 0; off >>= 1)
            acc[e] += __shfl_down_sync(0xffffffffu, acc[e], off);
    }
    if (lane == 0) {
#pragma unroll
        for (int e = 0; e < EE; e++) s_part[e][warp] = acc[e];
    }
    __syncthreads();

    if (tid < EE) {
        float v = 0.0f;
#pragma unroll
        for (int w = 0; w < TPB / 32; w++) v += s_part[tid][w];
        s_logit[tid] = v + __ldg(bias + tid);
    }
    __syncthreads();

    // ---- Phase 2: softmax -> log_probs -> gumbel top-2 -> aux term ----
    if (tid == 0) {
        float l[EE];
        float m = -1e30f;
#pragma unroll
        for (int e = 0; e < EE; e++) { l[e] = s_logit[e]; m = fmaxf(m, l[e]); }
        float p[EE];
        float sum = 0.0f;
#pragma unroll
        for (int e = 0; e < EE; e++) { p[e] = __expf(l[e] - m); sum += p[e]; }
        float inv = 1.0f / sum;
        float lp[EE];
#pragma unroll
        for (int e = 0; e < EE; e++) lp[e] = logf(p[e] * inv + 1e-9f);

        const float* nu = noise + (size_t)row * EE;
        float y[EE];
#pragma unroll
        for (int e = 0; e < EE; e++) {
            float u = __ldg(nu + e) * (1.0f - 2e-7f) + 1e-7f;
            float g = -logf(-logf(u));
            y[e] = lp[e] + g;
        }
        int i0 = 0;
#pragma unroll
        for (int e = 1; e < EE; e++) if (y[e] > y[i0]) i0 = e;
        int i1 = (i0 == 0) ? 1 : 0;
#pragma unroll
        for (int e = 0; e < EE; e++) if (e != i0 && y[e] > y[i1]) i1 = e;

        s_idx[0] = i0;
        s_idx[1] = i1;

        float adv = __ldg(rewards + row) - __ldg(baseline);
        atomicAdd(&g_aux_sum, (double)(adv * (lp[i0] + lp[i1])));
    }
    __syncthreads();

    // ---- Phase 3: combine gather (top-2 average) ----
    const int i0 = s_idx[0];
    const int i1 = s_idx[1];
    const float4* a = (const float4*)(eo + (size_t)i0 * (size_t)BT * DD + (size_t)row * DD);
    const float4* b = (const float4*)(eo + (size_t)i1 * (size_t)BT * DD + (size_t)row * DD);
    float4* o = (float4*)(out + (size_t)row * DD);

    for (int d = tid; d < DD / 4; d += TPB) {
        float4 va = __ldg(a + d);
        float4 vb = __ldg(b + d);
        float4 r;
        r.x = (va.x + vb.x) * 0.5f;
        r.y = (va.y + vb.y) * 0.5f;
        r.z = (va.z + vb.z) * 0.5f;
        r.w = (va.w + vb.w) * 0.5f;
        o[d] = r;
    }
}

__global__ void rlgate_fin_kernel(float* __restrict__ out, int out_size) {
    out[out_size - 1] = -(float)(g_aux_sum / (double)BT);
}

extern "C" void kernel_launch(void* const* d_in, const int* in_sizes, int n_in,
                              void* d_out, int out_size) {
    const float* x        = (const float*)d_in[0];
    const float* eo       = (const float*)d_in[1];
    const float* rewards  = (const float*)d_in[2];
    const float* W        = (const float*)d_in[3];
    const float* bias     = (const float*)d_in[4];
    const float* baseline = (const float*)d_in[5];
    const float* noise    = (const float*)d_in[6];
    // d_in[7] = top_k (hardcoded K=2 to match problem shapes)
    float* out = (float*)d_out;

    rlgate_init_kernel<<<1, 1>>>();
    rlgate_main_kernel<<<BT, TPB>>>(x, eo, rewards, W, bias, baseline, noise, out);
    rlgate_fin_kernel<<<1, 1>>>(out, out_size);
}

// round 4
// speedup vs baseline: 2.1813x; 2.1813x over previous
#include <cuda_runtime.h>
#include <math.h>

// Problem constants (B=4, T=2048, D=1024, E=8, K=2)
#define BT           8192
#define DD           1024
#define EE           8
#define TPB          256
#define ROWS_PER_CTA 16
#define NCTA         (BT / ROWS_PER_CTA)   // 512

__device__ float g_aux_part[NCTA];

__global__ __launch_bounds__(TPB) void rlgate_main_kernel(
    const float* __restrict__ x,          // [BT, D]
    const float* __restrict__ eo,         // [E, BT, D]
    const float* __restrict__ rewards,    // [BT]
    const float* __restrict__ W,          // [D, E]
    const float* __restrict__ bias,       // [E]
    const float* __restrict__ baseline,   // scalar
    const float* __restrict__ noise,      // [BT, E]
    float* __restrict__ out)              // [BT*D (+aux slot)]
{
    __shared__ float Wt[EE][DD];          // transposed gate weights, 32KB
    __shared__ float s_aux[ROWS_PER_CTA];

    const int tid  = threadIdx.x;
    const int lane = tid & 31;
    const int warp = tid >> 5;

    // ---- Load W [D,E] -> smem transposed Wt[E][D] (once per CTA) ----
    for (int idx = tid; idx < DD * EE; idx += TPB) {
        int d = idx >> 3;
        int e = idx & 7;
        Wt[e][d] = __ldg(W + idx);
    }
    __syncthreads();

    // Each warp handles 2 rows simultaneously (shares Wt reads across rows).
    const int r0 = blockIdx.x * ROWS_PER_CTA + warp * 2;
    const int r1 = r0 + 1;

    // ---- Phase 1: logits for both rows ----
    float acc0[EE], acc1[EE];
#pragma unroll
    for (int e = 0; e < EE; e++) { acc0[e] = 0.0f; acc1[e] = 0.0f; }

    const float4* x0  = (const float4*)(x + (size_t)r0 * DD);
    const float4* x1  = (const float4*)(x + (size_t)r1 * DD);
    const float4* Wt4 = (const float4*)Wt;   // Wt4[e*256 + j]

#pragma unroll
    for (int i = 0; i < 8; i++) {
        int j = lane + 32 * i;               // float4 index into row
        float4 xa = __ldg(x0 + j);
        float4 xb = __ldg(x1 + j);
#pragma unroll
        for (int e = 0; e < EE; e++) {
            float4 w = Wt4[e * (DD / 4) + j];  // conflict-free LDS.128
            acc0[e] = fmaf(xa.x, w.x, fmaf(xa.y, w.y, fmaf(xa.z, w.z, fmaf(xa.w, w.w, acc0[e]))));
            acc1[e] = fmaf(xb.x, w.x, fmaf(xb.y, w.y, fmaf(xb.z, w.z, fmaf(xb.w, w.w, acc1[e]))));
        }
    }

    // Warp all-reduce (xor) so every lane holds the full sums.
#pragma unroll
    for (int e = 0; e < EE; e++) {
#pragma unroll
        for (int off = 16; off > 0; off >>= 1) {
            acc0[e] += __shfl_xor_sync(0xffffffffu, acc0[e], off);
            acc1[e] += __shfl_xor_sync(0xffffffffu, acc1[e], off);
        }
    }

    // ---- Phase 2: lanes 0 and 1 do softmax/gumbel/top-2 for r0 / r1 ----
    int i0 = 0, i1 = 1;
    {
        float a[EE];
#pragma unroll
        for (int e = 0; e < EE; e++) a[e] = (lane == 1) ? acc1[e] : acc0[e];
        const int row = (lane == 1) ? r1 : r0;

        if (lane < 2) {
            float l[EE];
            float m = -1e30f;
#pragma unroll
            for (int e = 0; e < EE; e++) { l[e] = a[e] + __ldg(bias + e); m = fmaxf(m, l[e]); }
            float p[EE];
            float sum = 0.0f;
#pragma unroll
            for (int e = 0; e < EE; e++) { p[e] = __expf(l[e] - m); sum += p[e]; }
            float inv = 1.0f / sum;
            float lp[EE];
#pragma unroll
            for (int e = 0; e < EE; e++) lp[e] = logf(p[e] * inv + 1e-9f);

            const float* nu = noise + (size_t)row * EE;
            float y[EE];
#pragma unroll
            for (int e = 0; e < EE; e++) {
                float u = __ldg(nu + e) * (1.0f - 2e-7f) + 1e-7f;
                y[e] = lp[e] - logf(-logf(u));
            }
            i0 = 0;
#pragma unroll
            for (int e = 1; e < EE; e++) if (y[e] > y[i0]) i0 = e;
            i1 = (i0 == 0) ? 1 : 0;
#pragma unroll
            for (int e = 0; e < EE; e++) if (e != i0 && y[e] > y[i1]) i1 = e;

            float adv = __ldg(rewards + row) - __ldg(baseline);
            s_aux[warp * 2 + lane] = adv * (lp[i0] + lp[i1]);
        }
    }
    // Broadcast the selected expert indices for both rows.
    const int a0 = __shfl_sync(0xffffffffu, i0, 0);
    const int a1 = __shfl_sync(0xffffffffu, i1, 0);
    const int b0 = __shfl_sync(0xffffffffu, i0, 1);
    const int b1 = __shfl_sync(0xffffffffu, i1, 1);

    // ---- Phase 3: combine gather (top-2 average), 2 rows per warp ----
    {
        const float4* pa = (const float4*)(eo + ((size_t)a0 * BT + r0) * DD);
        const float4* pb = (const float4*)(eo + ((size_t)a1 * BT + r0) * DD);
        float4* o = (float4*)(out + (size_t)r0 * DD);
#pragma unroll
        for (int i = 0; i < 8; i++) {
            int j = lane + 32 * i;
            float4 va = __ldg(pa + j);
            float4 vb = __ldg(pb + j);
            float4 r;
            r.x = (va.x + vb.x) * 0.5f;
            r.y = (va.y + vb.y) * 0.5f;
            r.z = (va.z + vb.z) * 0.5f;
            r.w = (va.w + vb.w) * 0.5f;
            o[j] = r;
        }
    }
    {
        const float4* pa = (const float4*)(eo + ((size_t)b0 * BT + r1) * DD);
        const float4* pb = (const float4*)(eo + ((size_t)b1 * BT + r1) * DD);
        float4* o = (float4*)(out + (size_t)r1 * DD);
#pragma unroll
        for (int i = 0; i < 8; i++) {
            int j = lane + 32 * i;
            float4 va = __ldg(pa + j);
            float4 vb = __ldg(pb + j);
            float4 r;
            r.x = (va.x + vb.x) * 0.5f;
            r.y = (va.y + vb.y) * 0.5f;
            r.z = (va.z + vb.z) * 0.5f;
            r.w = (va.w + vb.w) * 0.5f;
            o[j] = r;
        }
    }

    // ---- Per-CTA aux partial (deterministic, no atomics) ----
    __syncthreads();
    if (tid == 0) {
        float s = 0.0f;
#pragma unroll
        for (int i = 0; i < ROWS_PER_CTA; i++) s += s_aux[i];
        g_aux_part[blockIdx.x] = s;
    }
}

__global__ void rlgate_fin_kernel(float* __restrict__ out, int out_size) {
    const int lane = threadIdx.x & 31;
    double s = 0.0;
#pragma unroll
    for (int k = 0; k < NCTA / 32; k++)
        s += (double)g_aux_part[lane + 32 * k];
#pragma unroll
    for (int off = 16; off > 0; off >>= 1)
        s += __shfl_xor_sync(0xffffffffu, s, off);
    if (lane == 0)
        out[out_size - 1] = -(float)(s / (double)BT);
}

extern "C" void kernel_launch(void* const* d_in, const int* in_sizes, int n_in,
                              void* d_out, int out_size) {
    const float* x        = (const float*)d_in[0];
    const float* eo       = (const float*)d_in[1];
    const float* rewards  = (const float*)d_in[2];
    const float* W        = (const float*)d_in[3];
    const float* bias     = (const float*)d_in[4];
    const float* baseline = (const float*)d_in[5];
    const float* noise    = (const float*)d_in[6];
    // d_in[7] = top_k (K=2 hardcoded to match problem shapes)
    float* out = (float*)d_out;

    rlgate_main_kernel<<<NCTA, TPB>>>(x, eo, rewards, W, bias, baseline, noise, out);
    rlgate_fin_kernel<<<1, 32>>>(out, out_size);
}

// round 5
// speedup vs baseline: 2.7367x; 1.2546x over previous
#include <cuda_runtime.h>
#include <math.h>

// Problem constants (B=4, T=2048, D=1024, E=8, K=2)
#define BT           8192
#define DD           1024
#define EE           8
#define TPB          256
#define ROWS_PER_CTA 16
#define NCTA         (BT / ROWS_PER_CTA)   // 512

__device__ float        g_aux_part[NCTA];
__device__ unsigned int g_ctr;             // zero-init; self-resets each launch

__global__ __launch_bounds__(TPB, 4) void rlgate_main_kernel(
    const float* __restrict__ x,          // [BT, D]
    const float* __restrict__ eo,         // [E, BT, D]
    const float* __restrict__ rewards,    // [BT]
    const float* __restrict__ W,          // [D, E]
    const float* __restrict__ bias,       // [E]
    const float* __restrict__ baseline,   // scalar
    const float* __restrict__ noise,      // [BT, E]
    float* __restrict__ out,              // [BT*D (+aux slot)]
    int out_size)
{
    __shared__ float Wt[EE][DD];          // transposed gate weights, 32KB
    __shared__ float s_aux[ROWS_PER_CTA];

    const int tid  = threadIdx.x;
    const int lane = tid & 31;
    const int warp = tid >> 5;

    // Each warp handles 2 rows (shares Wt reads across both).
    const int r0 = blockIdx.x * ROWS_PER_CTA + warp * 2;
    const int r1 = r0 + 1;

    const float4* x0 = (const float4*)(x + (size_t)r0 * DD);
    const float4* x1 = (const float4*)(x + (size_t)r1 * DD);

    // Prefetch first 2 x-iterations BEFORE the smem barrier (overlaps W fill).
    float4 xa0 = __ldg(x0 + lane);
    float4 xb0 = __ldg(x1 + lane);
    float4 xa1 = __ldg(x0 + lane + 32);
    float4 xb1 = __ldg(x1 + lane + 32);

    // ---- Load W [D,E] -> smem transposed Wt[E][D] (vectorized) ----
    {
        const float4* W4 = (const float4*)W;
#pragma unroll
        for (int k = 0; k < (DD * EE / 4) / TPB; k++) {
            int i = tid + k * TPB;
            float4 v = __ldg(W4 + i);
            int d  = i >> 1;
            int e0 = (i & 1) * 4;
            Wt[e0 + 0][d] = v.x;
            Wt[e0 + 1][d] = v.y;
            Wt[e0 + 2][d] = v.z;
            Wt[e0 + 3][d] = v.w;
        }
    }
    __syncthreads();

    // ---- Phase 1: logits for both rows (depth-2 pipelined) ----
    float acc0[EE], acc1[EE];
#pragma unroll
    for (int e = 0; e < EE; e++) { acc0[e] = 0.0f; acc1[e] = 0.0f; }

    const float4* Wt4 = (const float4*)Wt;   // Wt4[e*256 + j]

#pragma unroll
    for (int i = 0; i < 8; i++) {
        float4 a4 = (i & 1) ? xa1 : xa0;
        float4 b4 = (i & 1) ? xb1 : xb0;
        if (i < 6) {                          // prefetch i+2
            int jn = lane + 32 * (i + 2);
            if (i & 1) { xa1 = __ldg(x0 + jn); xb1 = __ldg(x1 + jn); }
            else       { xa0 = __ldg(x0 + jn); xb0 = __ldg(x1 + jn); }
        }
        int j = lane + 32 * i;
#pragma unroll
        for (int e = 0; e < EE; e++) {
            float4 w = Wt4[e * (DD / 4) + j];
            acc0[e] = fmaf(a4.x, w.x, fmaf(a4.y, w.y, fmaf(a4.z, w.z, fmaf(a4.w, w.w, acc0[e]))));
            acc1[e] = fmaf(b4.x, w.x, fmaf(b4.y, w.y, fmaf(b4.z, w.z, fmaf(b4.w, w.w, acc1[e]))));
        }
    }

#pragma unroll
    for (int e = 0; e < EE; e++) {
#pragma unroll
        for (int off = 16; off > 0; off >>= 1) {
            acc0[e] += __shfl_xor_sync(0xffffffffu, acc0[e], off);
            acc1[e] += __shfl_xor_sync(0xffffffffu, acc1[e], off);
        }
    }

    // ---- Phase 2: lanes 0/1 do softmax -> gumbel top-2 for r0/r1 ----
    int i0 = 0, i1 = 1;
    {
        float a[EE];
#pragma unroll
        for (int e = 0; e < EE; e++) a[e] = (lane == 1) ? acc1[e] : acc0[e];
        const int row = (lane == 1) ? r1 : r0;

        if (lane < 2) {
            float l[EE];
            float m = -1e30f;
#pragma unroll
            for (int e = 0; e < EE; e++) { l[e] = a[e] + __ldg(bias + e); m = fmaxf(m, l[e]); }
            float p[EE];
            float sum = 0.0f;
#pragma unroll
            for (int e = 0; e < EE; e++) { p[e] = __expf(l[e] - m); sum += p[e]; }
            float inv = 1.0f / sum;
            float lp[EE];
#pragma unroll
            for (int e = 0; e < EE; e++) lp[e] = logf(p[e] * inv + 1e-9f);

            const float* nu = noise + (size_t)row * EE;
            float y[EE];
#pragma unroll
            for (int e = 0; e < EE; e++) {
                float u = __ldg(nu + e) * (1.0f - 2e-7f) + 1e-7f;
                y[e] = lp[e] - logf(-logf(u));
            }
            i0 = 0;
#pragma unroll
            for (int e = 1; e < EE; e++) if (y[e] > y[i0]) i0 = e;
            i1 = (i0 == 0) ? 1 : 0;
#pragma unroll
            for (int e = 0; e < EE; e++) if (e != i0 && y[e] > y[i1]) i1 = e;

            float adv = __ldg(rewards + row) - __ldg(baseline);
            s_aux[warp * 2 + lane] = adv * (lp[i0] + lp[i1]);
        }
    }
    const int a0 = __shfl_sync(0xffffffffu, i0, 0);
    const int a1 = __shfl_sync(0xffffffffu, i1, 0);
    const int b0 = __shfl_sync(0xffffffffu, i0, 1);
    const int b1 = __shfl_sync(0xffffffffu, i1, 1);

    // ---- Aux partial + last-CTA election (before phase 3 so the finale
    //      overlaps other warps' gather streaming) ----
    __syncthreads();
    int is_last = 0;
    if (warp == 0) {
        if (lane == 0) {
            float s = 0.0f;
#pragma unroll
            for (int i = 0; i < ROWS_PER_CTA; i++) s += s_aux[i];
            g_aux_part[blockIdx.x] = s;
            __threadfence();
            unsigned p = atomicAdd(&g_ctr, 1u);
            is_last = (p == NCTA - 1);
        }
        is_last = __shfl_sync(0xffffffffu, is_last, 0);
        if (is_last) {
            double s = 0.0;
#pragma unroll
            for (int k = 0; k < NCTA / 32; k++)
                s += (double)__ldcg(&g_aux_part[lane + 32 * k]);
#pragma unroll
            for (int off = 16; off > 0; off >>= 1)
                s += __shfl_xor_sync(0xffffffffu, s, off);
            if (lane == 0) {
                out[out_size - 1] = -(float)(s / (double)BT);
                g_ctr = 0;                    // reset for next graph replay
            }
        }
    }

    // ---- Phase 3: combine gather (top-2 average), 2 rows per warp ----
    {
        const float4* pa = (const float4*)(eo + ((size_t)a0 * BT + r0) * DD);
        const float4* pb = (const float4*)(eo + ((size_t)a1 * BT + r0) * DD);
        const float4* pc = (const float4*)(eo + ((size_t)b0 * BT + r1) * DD);
        const float4* pd = (const float4*)(eo + ((size_t)b1 * BT + r1) * DD);
        float4* o0 = (float4*)(out + (size_t)r0 * DD);
        float4* o1 = (float4*)(out + (size_t)r1 * DD);
#pragma unroll
        for (int i = 0; i < 8; i++) {
            int j = lane + 32 * i;
            float4 va = __ldcs(pa + j);
            float4 vb = __ldcs(pb + j);
            float4 vc = __ldcs(pc + j);
            float4 vd = __ldcs(pd + j);
            float4 r0v, r1v;
            r0v.x = (va.x + vb.x) * 0.5f;
            r0v.y = (va.y + vb.y) * 0.5f;
            r0v.z = (va.z + vb.z) * 0.5f;
            r0v.w = (va.w + vb.w) * 0.5f;
            r1v.x = (vc.x + vd.x) * 0.5f;
            r1v.y = (vc.y + vd.y) * 0.5f;
            r1v.z = (vc.z + vd.z) * 0.5f;
            r1v.w = (vc.w + vd.w) * 0.5f;
            __stcs(o0 + j, r0v);
            __stcs(o1 + j, r1v);
        }
    }
}

extern "C" void kernel_launch(void* const* d_in, const int* in_sizes, int n_in,
                              void* d_out, int out_size) {
    const float* x        = (const float*)d_in[0];
    const float* eo       = (const float*)d_in[1];
    const float* rewards  = (const float*)d_in[2];
    const float* W        = (const float*)d_in[3];
    const float* bias     = (const float*)d_in[4];
    const float* baseline = (const float*)d_in[5];
    const float* noise    = (const float*)d_in[6];
    // d_in[7] = top_k (K=2 hardcoded to match problem shapes)
    float* out = (float*)d_out;

    rlgate_main_kernel<<<NCTA, TPB>>>(x, eo, rewards, W, bias, baseline, noise,
                                      out, out_size);
}